// round 1
// baseline (speedup 1.0000x reference)
#include <cuda_runtime.h>
#include <stdint.h>

// LSTM, B=4096, T=2048, I=1, H=10.
// Design: 2 batch elements packed per lane via fma.rn.f32x2; 10 lanes per
// batch-pair (one hidden unit each); 3 groups per warp; h broadcast via
// warp shuffles; weights/state fully register-resident.

#define FULL_MASK 0xFFFFFFFFu

constexpr int Bv = 4096;
constexpr int Tv = 2048;
constexpr int Hv = 10;
constexpr int NGROUPS = Bv / 2;            // 2048 batch-pairs
constexpr int GROUPS_PER_BLOCK = 15;       // 5 warps * 3 groups
constexpr int THREADS = 160;

__device__ __forceinline__ unsigned long long pack2(float lo, float hi) {
    unsigned long long r;
    asm("mov.b64 %0, {%1, %2};" : "=l"(r) : "f"(lo), "f"(hi));
    return r;
}
__device__ __forceinline__ void unpack2(unsigned long long v, float& lo, float& hi) {
    asm("mov.b64 {%0, %1}, %2;" : "=f"(lo), "=f"(hi) : "l"(v));
}
// Blackwell packed fp32 FMA: d = a*b + c per 32-bit half.
__device__ __forceinline__ unsigned long long fma2(unsigned long long a,
                                                   unsigned long long b,
                                                   unsigned long long c) {
    unsigned long long d;
    asm("fma.rn.f32x2 %0, %1, %2, %3;" : "=l"(d) : "l"(a), "l"(b), "l"(c));
    return d;
}
__device__ __forceinline__ float ex2a(float x) {
    float r; asm("ex2.approx.f32 %0, %1;" : "=f"(r) : "f"(x)); return r;
}
__device__ __forceinline__ float rcpa(float x) {
    float r; asm("rcp.approx.f32 %0, %1;" : "=f"(r) : "f"(x)); return r;
}
// Accurate-enough sigmoid/tanh (~1e-7 rel err): 2 MUFU each.
__device__ __forceinline__ float sigm(float x) {
    return rcpa(1.0f + ex2a(-1.4426950408889634f * x));
}
__device__ __forceinline__ float tanh_f(float x) {
    float t = ex2a(2.8853900817779268f * x);       // e^{2x}
    return fmaf(-2.0f, rcpa(t + 1.0f), 1.0f);      // 1 - 2/(e^{2x}+1)
}

__global__ void __launch_bounds__(THREADS, 1)
lstm_kernel(const float* __restrict__ x,
            const float* __restrict__ W_ih,   // [40,1]
            const float* __restrict__ W_hh,   // [40,10]
            const float* __restrict__ b_ih,   // [40]
            const float* __restrict__ b_hh,   // [40]
            const float* __restrict__ W_out,  // [1,10]
            const float* __restrict__ b_out,  // [1]
            float* __restrict__ out)          // [4096]
{
    const int warp = threadIdx.x >> 5;
    const int lane = threadIdx.x & 31;
    const int g    = lane / 10;               // group within warp, 0..2 (3 = idle lanes 30,31)
    const int j    = lane - g * 10;           // hidden unit owned by this lane
    const int base = g * 10;                  // shuffle base lane of this group
    const int slot = blockIdx.x * GROUPS_PER_BLOCK + warp * 3 + g;
    const bool active = (g < 3) && (slot < NGROUPS);
    const int s  = active ? slot : 0;         // clamp so idle lanes do safe loads
    const int bA = 2 * s;
    const int bB = 2 * s + 1;

    // ---- Load per-lane weights (rows q*10+j, gate order i,f,g,o), duplicated
    // ---- into both f32x2 halves. 40 packed weights = 80 regs.
    unsigned long long w2[4][10], bias2[4], wih2[4];
#pragma unroll
    for (int q = 0; q < 4; q++) {
        const int row = q * 10 + j;
        const float bb = b_ih[row] + b_hh[row];
        bias2[q] = pack2(bb, bb);
        const float wi = W_ih[row];           // I == 1
        wih2[q] = pack2(wi, wi);
#pragma unroll
        for (int k = 0; k < 10; k++) {
            const float w = W_hh[row * Hv + k];
            w2[q][k] = pack2(w, w);
        }
    }

    // ---- State: h broadcast copies (packed {hA[k], hB[k]}), c scalar per batch.
    unsigned long long h2[10];
#pragma unroll
    for (int k = 0; k < 10; k++) h2[k] = 0ull;
    float cA = 0.f, cB = 0.f, hA = 0.f, hB = 0.f;

    const float4* xA4 = reinterpret_cast<const float4*>(x + (size_t)bA * Tv);
    const float4* xB4 = reinterpret_cast<const float4*>(x + (size_t)bB * Tv);
    float4 nA = xA4[0], nB = xB4[0];          // double-buffered x (4 steps/load)

    for (int t0 = 0; t0 < Tv; t0 += 4) {
        const float4 curA = nA, curB = nB;
        const int nxt = (t0 >> 2) + 1;
        if (nxt < Tv / 4) { nA = xA4[nxt]; nB = xB4[nxt]; }

#pragma unroll
        for (int u = 0; u < 4; u++) {
            const float xa = (u == 0) ? curA.x : (u == 1) ? curA.y : (u == 2) ? curA.z : curA.w;
            const float xb = (u == 0) ? curB.x : (u == 1) ? curB.y : (u == 2) ? curB.z : curB.w;
            const unsigned long long x2 = pack2(xa, xb);

            // 4 independent gate chains, 11 FFMA2 each (ILP=4 keeps FMA pipe full).
            unsigned long long ai = fma2(x2, wih2[0], bias2[0]);
            unsigned long long af = fma2(x2, wih2[1], bias2[1]);
            unsigned long long ag = fma2(x2, wih2[2], bias2[2]);
            unsigned long long ao = fma2(x2, wih2[3], bias2[3]);
#pragma unroll
            for (int k = 0; k < 10; k++) {
                ai = fma2(h2[k], w2[0][k], ai);
                af = fma2(h2[k], w2[1][k], af);
                ag = fma2(h2[k], w2[2][k], ag);
                ao = fma2(h2[k], w2[3][k], ao);
            }

            float iA, iB, fA, fB, gA, gB, oA, oB;
            unpack2(ai, iA, iB);
            unpack2(af, fA, fB);
            unpack2(ag, gA, gB);
            unpack2(ao, oA, oB);

            iA = sigm(iA); iB = sigm(iB);
            fA = sigm(fA); fB = sigm(fB);
            gA = tanh_f(gA); gB = tanh_f(gB);
            oA = sigm(oA); oB = sigm(oB);

            cA = fmaf(fA, cA, iA * gA);
            cB = fmaf(fB, cB, iB * gB);
            hA = oA * tanh_f(cA);
            hB = oB * tanh_f(cB);

            // Broadcast h within the 10-lane group for the next step.
#pragma unroll
            for (int k = 0; k < 10; k++) {
                const float lA = __shfl_sync(FULL_MASK, hA, base + k);
                const float lB = __shfl_sync(FULL_MASK, hB, base + k);
                h2[k] = pack2(lA, lB);
            }
        }
    }

    // ---- Epilogue: out[b] = h_T . W_out + b_out
    const float wo = W_out[j];
    const float pA = hA * wo;
    const float pB = hB * wo;
    float sA = 0.f, sB = 0.f;
#pragma unroll
    for (int k = 0; k < 10; k++) {
        sA += __shfl_sync(FULL_MASK, pA, base + k);
        sB += __shfl_sync(FULL_MASK, pB, base + k);
    }
    if (active && j == 0) {
        const float bo = b_out[0];
        out[bA] = sA + bo;
        out[bB] = sB + bo;
    }
}

extern "C" void kernel_launch(void* const* d_in, const int* in_sizes, int n_in,
                              void* d_out, int out_size) {
    (void)in_sizes; (void)n_in; (void)out_size;
    const float* x     = (const float*)d_in[0];
    const float* W_ih  = (const float*)d_in[1];
    const float* W_hh  = (const float*)d_in[2];
    const float* b_ih  = (const float*)d_in[3];
    const float* b_hh  = (const float*)d_in[4];
    const float* W_out = (const float*)d_in[5];
    const float* b_out = (const float*)d_in[6];
    float* out = (float*)d_out;

    const int nblocks = (NGROUPS + GROUPS_PER_BLOCK - 1) / GROUPS_PER_BLOCK; // 137
    lstm_kernel<<<nblocks, THREADS>>>(x, W_ih, W_hh, b_ih, b_hh, W_out, b_out, out);
}

// round 2
// speedup vs baseline: 1.4501x; 1.4501x over previous
#include <cuda_runtime.h>
#include <stdint.h>

// LSTM, B=4096, T=2048, I=1, H=10.
// Round 2: all activations via MUFU.TANH (sigmoid = 0.5*tanh(a/2)+0.5 with the
// 0.5 folded into i/f/o weight rows), split matvec chains (depth 11 -> ~6),
// 64-bit h shuffles. 2 batches per lane via fma.rn.f32x2; 10 lanes per
// batch-pair; 3 groups per warp; weights/state fully register-resident.

#define FULL_MASK 0xFFFFFFFFu

constexpr int Bv = 4096;
constexpr int Tv = 2048;
constexpr int Hv = 10;
constexpr int NGROUPS = Bv / 2;            // 2048 batch-pairs
constexpr int GROUPS_PER_BLOCK = 15;       // 5 warps * 3 groups
constexpr int THREADS = 160;

__device__ __forceinline__ unsigned long long pack2(float lo, float hi) {
    unsigned long long r;
    asm("mov.b64 %0, {%1, %2};" : "=l"(r) : "f"(lo), "f"(hi));
    return r;
}
__device__ __forceinline__ void unpack2(unsigned long long v, float& lo, float& hi) {
    asm("mov.b64 {%0, %1}, %2;" : "=f"(lo), "=f"(hi) : "l"(v));
}
// Blackwell packed fp32 ops, one issue per 2 lanes of data.
__device__ __forceinline__ unsigned long long fma2(unsigned long long a,
                                                   unsigned long long b,
                                                   unsigned long long c) {
    unsigned long long d;
    asm("fma.rn.f32x2 %0, %1, %2, %3;" : "=l"(d) : "l"(a), "l"(b), "l"(c));
    return d;
}
__device__ __forceinline__ unsigned long long mul2(unsigned long long a,
                                                   unsigned long long b) {
    unsigned long long d;
    asm("mul.rn.f32x2 %0, %1, %2;" : "=l"(d) : "l"(a), "l"(b));
    return d;
}
__device__ __forceinline__ unsigned long long add2(unsigned long long a,
                                                   unsigned long long b) {
    unsigned long long d;
    asm("add.rn.f32x2 %0, %1, %2;" : "=l"(d) : "l"(a), "l"(b));
    return d;
}
// Hardware tanh: single MUFU.TANH, lat ~16.
__device__ __forceinline__ float tanh_a(float x) {
    float r; asm("tanh.approx.f32 %0, %1;" : "=f"(r) : "f"(x)); return r;
}
// sigmoid(a) where the input was pre-scaled: caller passes a/2.
__device__ __forceinline__ float sigm_half(float a_half) {
    return fmaf(0.5f, tanh_a(a_half), 0.5f);
}

__global__ void __launch_bounds__(THREADS, 1)
lstm_kernel(const float* __restrict__ x,
            const float* __restrict__ W_ih,   // [40,1]
            const float* __restrict__ W_hh,   // [40,10]
            const float* __restrict__ b_ih,   // [40]
            const float* __restrict__ b_hh,   // [40]
            const float* __restrict__ W_out,  // [1,10]
            const float* __restrict__ b_out,  // [1]
            float* __restrict__ out)          // [4096]
{
    const int warp = threadIdx.x >> 5;
    const int lane = threadIdx.x & 31;
    const int g    = lane / 10;               // group within warp, 0..2 (3 = idle)
    const int j    = lane - g * 10;           // hidden unit owned by this lane
    const int base = g * 10;                  // shuffle base lane of this group
    const int slot = blockIdx.x * GROUPS_PER_BLOCK + warp * 3 + g;
    const bool active = (g < 3) && (slot < NGROUPS);
    const int s  = active ? slot : 0;         // clamp so idle lanes do safe loads
    const int bA = 2 * s;
    const int bB = 2 * s + 1;

    // ---- Per-lane weights (rows q*10+j, gate order i,f,g,o). Rows for the
    // ---- sigmoid gates (q=0,1,3) are pre-scaled by 0.5 so sigmoid becomes
    // ---- one TANH + one FMA. Duplicated into both f32x2 halves.
    unsigned long long w2[4][10], bias2[4], wih2[4];
#pragma unroll
    for (int q = 0; q < 4; q++) {
        const float scale = (q == 2) ? 1.0f : 0.5f;
        const int row = q * 10 + j;
        const float bb = (b_ih[row] + b_hh[row]) * scale;
        bias2[q] = pack2(bb, bb);
        const float wi = W_ih[row] * scale;   // I == 1
        wih2[q] = pack2(wi, wi);
#pragma unroll
        for (int k = 0; k < 10; k++) {
            const float w = W_hh[row * Hv + k] * scale;
            w2[q][k] = pack2(w, w);
        }
    }

    // ---- State: packed h broadcast copies {hA[k], hB[k]}, scalar c per batch.
    unsigned long long h2[10];
#pragma unroll
    for (int k = 0; k < 10; k++) h2[k] = 0ull;
    float cA = 0.f, cB = 0.f, hA = 0.f, hB = 0.f;

    const float4* xA4 = reinterpret_cast<const float4*>(x + (size_t)bA * Tv);
    const float4* xB4 = reinterpret_cast<const float4*>(x + (size_t)bB * Tv);
    float4 nA = xA4[0], nB = xB4[0];          // double-buffered x (4 steps/load)

    for (int t0 = 0; t0 < Tv; t0 += 4) {
        const float4 curA = nA, curB = nB;
        const int nxt = (t0 >> 2) + 1;
        if (nxt < Tv / 4) { nA = xA4[nxt]; nB = xB4[nxt]; }

#pragma unroll
        for (int u = 0; u < 4; u++) {
            const float xa = (u == 0) ? curA.x : (u == 1) ? curA.y : (u == 2) ? curA.z : curA.w;
            const float xb = (u == 0) ? curB.x : (u == 1) ? curB.y : (u == 2) ? curB.z : curB.w;
            const unsigned long long x2 = pack2(xa, xb);

            // 8 independent partial chains (2 per gate), depth <= 6, then add.
            unsigned long long aA[4], aB[4];
#pragma unroll
            for (int q = 0; q < 4; q++) {
                aA[q] = fma2(x2, wih2[q], bias2[q]);
                aB[q] = mul2(h2[5], w2[q][5]);
            }
#pragma unroll
            for (int k = 0; k < 5; k++) {
#pragma unroll
                for (int q = 0; q < 4; q++) {
                    aA[q] = fma2(h2[k], w2[q][k], aA[q]);
                    if (k < 4) aB[q] = fma2(h2[6 + k], w2[q][6 + k], aB[q]);
                }
            }
            const unsigned long long ai = add2(aA[0], aB[0]);
            const unsigned long long af = add2(aA[1], aB[1]);
            const unsigned long long ag = add2(aA[2], aB[2]);
            const unsigned long long ao = add2(aA[3], aB[3]);

            float iA, iB, fA, fB, gA, gB, oA, oB;
            unpack2(ai, iA, iB);
            unpack2(af, fA, fB);
            unpack2(ag, gA, gB);
            unpack2(ao, oA, oB);

            iA = sigm_half(iA); iB = sigm_half(iB);   // inputs already a/2
            fA = sigm_half(fA); fB = sigm_half(fB);
            gA = tanh_a(gA);    gB = tanh_a(gB);
            oA = sigm_half(oA); oB = sigm_half(oB);

            cA = fmaf(fA, cA, iA * gA);
            cB = fmaf(fB, cB, iB * gB);
            hA = oA * tanh_a(cA);
            hB = oB * tanh_a(cB);

            // One packed register, shuffled as 64-bit (2 SHFLs per k, no repack).
            const unsigned long long hself = pack2(hA, hB);
#pragma unroll
            for (int k = 0; k < 10; k++) {
                h2[k] = __shfl_sync(FULL_MASK, hself, base + k);
            }
        }
    }

    // ---- Epilogue: out[b] = h_T . W_out + b_out
    const float wo = W_out[j];
    const float pA = hA * wo;
    const float pB = hB * wo;
    float sA = 0.f, sB = 0.f;
#pragma unroll
    for (int k = 0; k < 10; k++) {
        sA += __shfl_sync(FULL_MASK, pA, base + k);
        sB += __shfl_sync(FULL_MASK, pB, base + k);
    }
    if (active && j == 0) {
        const float bo = b_out[0];
        out[bA] = sA + bo;
        out[bB] = sB + bo;
    }
}

extern "C" void kernel_launch(void* const* d_in, const int* in_sizes, int n_in,
                              void* d_out, int out_size) {
    (void)in_sizes; (void)n_in; (void)out_size;
    const float* x     = (const float*)d_in[0];
    const float* W_ih  = (const float*)d_in[1];
    const float* W_hh  = (const float*)d_in[2];
    const float* b_ih  = (const float*)d_in[3];
    const float* b_hh  = (const float*)d_in[4];
    const float* W_out = (const float*)d_in[5];
    const float* b_out = (const float*)d_in[6];
    float* out = (float*)d_out;

    const int nblocks = (NGROUPS + GROUPS_PER_BLOCK - 1) / GROUPS_PER_BLOCK; // 137
    lstm_kernel<<<nblocks, THREADS>>>(x, W_ih, W_hh, b_ih, b_hh, W_out, b_out, out);
}

// round 3
// speedup vs baseline: 1.5205x; 1.0486x over previous
#include <cuda_runtime.h>
#include <stdint.h>

// LSTM, B=4096, T=2048, I=1, H=10.
// Round 3: uniform 2 warps/SMSP (8 warps/block, grid 86); single-chain matvec;
// packed f32x2 epilogue with h'=2h folding (W_hh/W_out pre-halved) so each
// sigmoid costs 1 TANH + amortized packed FMA. 2 batches/lane via fma.rn.f32x2,
// 10 lanes per batch-pair, 3 pairs/warp, all state register-resident.

#define FULL_MASK 0xFFFFFFFFu

constexpr int Bv = 4096;
constexpr int Tv = 2048;
constexpr int Hv = 10;
constexpr int NGROUPS = Bv / 2;            // 2048 batch-pairs
constexpr int WARPS_PER_BLOCK = 8;
constexpr int GROUPS_PER_BLOCK = WARPS_PER_BLOCK * 3;  // 24
constexpr int THREADS = WARPS_PER_BLOCK * 32;          // 256

__device__ __forceinline__ unsigned long long pack2(float lo, float hi) {
    unsigned long long r;
    asm("mov.b64 %0, {%1, %2};" : "=l"(r) : "f"(lo), "f"(hi));
    return r;
}
__device__ __forceinline__ void unpack2(unsigned long long v, float& lo, float& hi) {
    asm("mov.b64 {%0, %1}, %2;" : "=f"(lo), "=f"(hi) : "l"(v));
}
__device__ __forceinline__ unsigned long long fma2(unsigned long long a,
                                                   unsigned long long b,
                                                   unsigned long long c) {
    unsigned long long d;
    asm("fma.rn.f32x2 %0, %1, %2, %3;" : "=l"(d) : "l"(a), "l"(b), "l"(c));
    return d;
}
__device__ __forceinline__ unsigned long long mul2(unsigned long long a,
                                                   unsigned long long b) {
    unsigned long long d;
    asm("mul.rn.f32x2 %0, %1, %2;" : "=l"(d) : "l"(a), "l"(b));
    return d;
}
__device__ __forceinline__ float tanh_a(float x) {
    float r; asm("tanh.approx.f32 %0, %1;" : "=f"(r) : "f"(x)); return r;
}

__global__ void __launch_bounds__(THREADS, 1)
lstm_kernel(const float* __restrict__ x,
            const float* __restrict__ W_ih,   // [40,1]
            const float* __restrict__ W_hh,   // [40,10]
            const float* __restrict__ b_ih,   // [40]
            const float* __restrict__ b_hh,   // [40]
            const float* __restrict__ W_out,  // [1,10]
            const float* __restrict__ b_out,  // [1]
            float* __restrict__ out)          // [4096]
{
    const int warp = threadIdx.x >> 5;
    const int lane = threadIdx.x & 31;
    // Whole-warp early exit when all 3 of its groups are out of range.
    if (blockIdx.x * GROUPS_PER_BLOCK + warp * 3 >= NGROUPS) return;

    const int g    = lane / 10;               // group within warp, 0..2 (3 = idle)
    const int j    = lane - g * 10;           // hidden unit owned by this lane
    const int base = g * 10;
    const int slot = blockIdx.x * GROUPS_PER_BLOCK + warp * 3 + g;
    const bool active = (g < 3) && (slot < NGROUPS);
    const int s  = active ? slot : 0;
    const int bA = 2 * s;
    const int bB = 2 * s + 1;

    // ---- Per-lane weights (rows q*10+j, gate order i,f,g,o).
    // Sigmoid gates (q=0,1,3): inputs pre-scaled by 0.5 (sigm(a)=0.5*tanh(a/2)+0.5).
    // h is stored as h' = 2h, so W_hh additionally gets *0.5.
    unsigned long long w2[4][10], bias2[4], wih2[4];
#pragma unroll
    for (int q = 0; q < 4; q++) {
        const float gs = (q == 2) ? 1.0f : 0.5f;   // gate input scale
        const int row = q * 10 + j;
        const float bb = (b_ih[row] + b_hh[row]) * gs;
        bias2[q] = pack2(bb, bb);
        const float wi = W_ih[row] * gs;           // I == 1
        wih2[q] = pack2(wi, wi);
        const float hs = gs * 0.5f;                // fold h'=2h
#pragma unroll
        for (int k = 0; k < 10; k++) {
            const float w = W_hh[row * Hv + k] * hs;
            w2[q][k] = pack2(w, w);
        }
    }
    const unsigned long long half2 = pack2(0.5f, 0.5f);

    // ---- State: packed h' broadcast copies, packed c.
    unsigned long long h2[10];
#pragma unroll
    for (int k = 0; k < 10; k++) h2[k] = 0ull;
    unsigned long long c2 = 0ull;
    float hA = 0.f, hB = 0.f;                      // h' of own unit (for epilogue)

    const float4* xA4 = reinterpret_cast<const float4*>(x + (size_t)bA * Tv);
    const float4* xB4 = reinterpret_cast<const float4*>(x + (size_t)bB * Tv);
    float4 nA = xA4[0], nB = xB4[0];               // double-buffered x

    for (int t0 = 0; t0 < Tv; t0 += 4) {
        const float4 curA = nA, curB = nB;
        const int nxt = (t0 >> 2) + 1;
        if (nxt < Tv / 4) { nA = xA4[nxt]; nB = xB4[nxt]; }

#pragma unroll
        for (int u = 0; u < 4; u++) {
            const float xa = (u == 0) ? curA.x : (u == 1) ? curA.y : (u == 2) ? curA.z : curA.w;
            const float xb = (u == 0) ? curB.x : (u == 1) ? curB.y : (u == 2) ? curB.z : curB.w;
            const unsigned long long x2 = pack2(xa, xb);

            // 4 independent 11-deep chains (one per gate).
            unsigned long long ai = fma2(x2, wih2[0], bias2[0]);
            unsigned long long af = fma2(x2, wih2[1], bias2[1]);
            unsigned long long ag = fma2(x2, wih2[2], bias2[2]);
            unsigned long long ao = fma2(x2, wih2[3], bias2[3]);
#pragma unroll
            for (int k = 0; k < 10; k++) {
                ai = fma2(h2[k], w2[0][k], ai);
                af = fma2(h2[k], w2[1][k], af);
                ag = fma2(h2[k], w2[2][k], ag);
                ao = fma2(h2[k], w2[3][k], ao);
            }

            float aiA, aiB, afA, afB, agA, agB, aoA, aoB;
            unpack2(ai, aiA, aiB);
            unpack2(af, afA, afB);
            unpack2(ag, agA, agB);
            unpack2(ao, aoA, aoB);

            // 8 independent TANH (inputs already gate-scaled).
            const float tiA = tanh_a(aiA), tiB = tanh_a(aiB);
            const float tfA = tanh_a(afA), tfB = tanh_a(afB);
            const float tgA = tanh_a(agA), tgB = tanh_a(agB);
            const float toA = tanh_a(aoA), toB = tanh_a(aoB);

            // Packed epilogue: i = 0.5*ti + 0.5, f = 0.5*tf + 0.5,
            // c = f*c + i*g, h' = 2h = to*tanh(c) + tanh(c).
            const unsigned long long ti2 = pack2(tiA, tiB);
            const unsigned long long tf2 = pack2(tfA, tfB);
            const unsigned long long tg2 = pack2(tgA, tgB);
            const unsigned long long i2  = fma2(half2, ti2, half2);
            const unsigned long long f2  = fma2(half2, tf2, half2);
            const unsigned long long ig2 = mul2(i2, tg2);
            c2 = fma2(f2, c2, ig2);

            float cA, cB;
            unpack2(c2, cA, cB);
            const float tcA = tanh_a(cA);
            const float tcB = tanh_a(cB);
            hA = fmaf(toA, tcA, tcA);              // h' = 2h
            hB = fmaf(toB, tcB, tcB);

            const unsigned long long hself = pack2(hA, hB);
#pragma unroll
            for (int k = 0; k < 10; k++) {
                h2[k] = __shfl_sync(FULL_MASK, hself, base + k);
            }
        }
    }

    // ---- Epilogue: out[b] = h . W_out + b_out, with h = 0.5*h'.
    const float wo = W_out[j] * 0.5f;
    const float pA = hA * wo;
    const float pB = hB * wo;
    float sA = 0.f, sB = 0.f;
#pragma unroll
    for (int k = 0; k < 10; k++) {
        sA += __shfl_sync(FULL_MASK, pA, base + k);
        sB += __shfl_sync(FULL_MASK, pB, base + k);
    }
    if (active && j == 0) {
        const float bo = b_out[0];
        out[bA] = sA + bo;
        out[bB] = sB + bo;
    }
}

extern "C" void kernel_launch(void* const* d_in, const int* in_sizes, int n_in,
                              void* d_out, int out_size) {
    (void)in_sizes; (void)n_in; (void)out_size;
    const float* x     = (const float*)d_in[0];
    const float* W_ih  = (const float*)d_in[1];
    const float* W_hh  = (const float*)d_in[2];
    const float* b_ih  = (const float*)d_in[3];
    const float* b_hh  = (const float*)d_in[4];
    const float* W_out = (const float*)d_in[5];
    const float* b_out = (const float*)d_in[6];
    float* out = (float*)d_out;

    const int nblocks = (NGROUPS + GROUPS_PER_BLOCK - 1) / GROUPS_PER_BLOCK; // 86
    lstm_kernel<<<nblocks, THREADS>>>(x, W_ih, W_hh, b_ih, b_hh, W_out, b_out, out);
}

// round 4
// speedup vs baseline: 1.6131x; 1.0609x over previous
#include <cuda_runtime.h>
#include <stdint.h>

// LSTM, B=4096, T=2048, I=1, H=10.
// Round 4: h broadcast via shared memory (STS.64 + syncwarp + 5x LDS.128,
// double-buffered by step parity) instead of 20 SHFLs per step.
// 2 batches/lane via fma.rn.f32x2; 10 lanes per batch-pair; 3 pairs/warp;
// sigmoid = 0.5*tanh(a/2)+0.5 folded into weights; h stored as h'=2h.

#define FULL_MASK 0xFFFFFFFFu

constexpr int Bv = 4096;
constexpr int Tv = 2048;
constexpr int Hv = 10;
constexpr int NGROUPS = Bv / 2;            // 2048 batch-pairs
constexpr int WARPS_PER_BLOCK = 8;
constexpr int GROUPS_PER_BLOCK = WARPS_PER_BLOCK * 3;  // 24
constexpr int THREADS = WARPS_PER_BLOCK * 32;          // 256

__device__ __forceinline__ unsigned long long pack2(float lo, float hi) {
    unsigned long long r;
    asm("mov.b64 %0, {%1, %2};" : "=l"(r) : "f"(lo), "f"(hi));
    return r;
}
__device__ __forceinline__ void unpack2(unsigned long long v, float& lo, float& hi) {
    asm("mov.b64 {%0, %1}, %2;" : "=f"(lo), "=f"(hi) : "l"(v));
}
__device__ __forceinline__ unsigned long long fma2(unsigned long long a,
                                                   unsigned long long b,
                                                   unsigned long long c) {
    unsigned long long d;
    asm("fma.rn.f32x2 %0, %1, %2, %3;" : "=l"(d) : "l"(a), "l"(b), "l"(c));
    return d;
}
__device__ __forceinline__ unsigned long long mul2(unsigned long long a,
                                                   unsigned long long b) {
    unsigned long long d;
    asm("mul.rn.f32x2 %0, %1, %2;" : "=l"(d) : "l"(a), "l"(b));
    return d;
}
__device__ __forceinline__ float tanh_a(float x) {
    float r; asm("tanh.approx.f32 %0, %1;" : "=f"(r) : "f"(x)); return r;
}

__global__ void __launch_bounds__(THREADS, 1)
lstm_kernel(const float* __restrict__ x,
            const float* __restrict__ W_ih,   // [40,1]
            const float* __restrict__ W_hh,   // [40,10]
            const float* __restrict__ b_ih,   // [40]
            const float* __restrict__ b_hh,   // [40]
            const float* __restrict__ W_out,  // [1,10]
            const float* __restrict__ b_out,  // [1]
            float* __restrict__ out)          // [4096]
{
    // Double-buffered h exchange: [parity][warp][group][unit], 12-ull stride
    // (96B) keeps LDS.128 16B-aligned and groups on distinct banks.
    __shared__ __align__(16) unsigned long long hbuf[2][WARPS_PER_BLOCK][4][12];

    const int warp = threadIdx.x >> 5;
    const int lane = threadIdx.x & 31;
    // Whole-warp early exit (no block-wide barriers are used).
    if (blockIdx.x * GROUPS_PER_BLOCK + warp * 3 >= NGROUPS) return;

    const int g    = lane / 10;               // 0..2 real groups, 3 = idle lanes
    const int j    = lane - g * 10;           // hidden unit owned by this lane
    const int base = g * 10;
    const int slot = blockIdx.x * GROUPS_PER_BLOCK + warp * 3 + g;
    const bool active = (g < 3) && (slot < NGROUPS);
    const int s  = active ? slot : 0;
    const int bA = 2 * s;
    const int bB = 2 * s + 1;

    // ---- Per-lane weights (rows q*10+j, gate order i,f,g,o).
    // Sigmoid gates (q=0,1,3): pre-scaled by 0.5. h is h'=2h -> W_hh *0.5 more.
    unsigned long long w2[4][10], bias2[4], wih2[4];
#pragma unroll
    for (int q = 0; q < 4; q++) {
        const float gs = (q == 2) ? 1.0f : 0.5f;
        const int row = q * 10 + j;
        const float bb = (b_ih[row] + b_hh[row]) * gs;
        bias2[q] = pack2(bb, bb);
        const float wi = W_ih[row] * gs;           // I == 1
        wih2[q] = pack2(wi, wi);
        const float hs = gs * 0.5f;
#pragma unroll
        for (int k = 0; k < 10; k++) {
            const float w = W_hh[row * Hv + k] * hs;
            w2[q][k] = pack2(w, w);
        }
    }
    const unsigned long long half2 = pack2(0.5f, 0.5f);

    // ---- State
    unsigned long long h2[10];
#pragma unroll
    for (int k = 0; k < 10; k++) h2[k] = 0ull;
    unsigned long long c2 = 0ull;
    float hA = 0.f, hB = 0.f;                      // own unit h' (for epilogue)

    unsigned long long* myst0 = &hbuf[0][warp][g][j];
    unsigned long long* myst1 = &hbuf[1][warp][g][j];
    const ulonglong2* grp0 = reinterpret_cast<const ulonglong2*>(&hbuf[0][warp][g][0]);
    const ulonglong2* grp1 = reinterpret_cast<const ulonglong2*>(&hbuf[1][warp][g][0]);

    const float4* xA4 = reinterpret_cast<const float4*>(x + (size_t)bA * Tv);
    const float4* xB4 = reinterpret_cast<const float4*>(x + (size_t)bB * Tv);
    float4 nA = xA4[0], nB = xB4[0];               // double-buffered x

    for (int t0 = 0; t0 < Tv; t0 += 4) {
        const float4 curA = nA, curB = nB;
        const int nxt = (t0 >> 2) + 1;
        if (nxt < Tv / 4) { nA = xA4[nxt]; nB = xB4[nxt]; }

#pragma unroll
        for (int u = 0; u < 4; u++) {
            const float xa = (u == 0) ? curA.x : (u == 1) ? curA.y : (u == 2) ? curA.z : curA.w;
            const float xb = (u == 0) ? curB.x : (u == 1) ? curB.y : (u == 2) ? curB.z : curB.w;
            const unsigned long long x2 = pack2(xa, xb);

            // 4 independent 11-deep chains; g and i ordered first (they feed
            // the deepest epilogue path).
            unsigned long long ag = fma2(x2, wih2[2], bias2[2]);
            unsigned long long ai = fma2(x2, wih2[0], bias2[0]);
            unsigned long long af = fma2(x2, wih2[1], bias2[1]);
            unsigned long long ao = fma2(x2, wih2[3], bias2[3]);
#pragma unroll
            for (int k = 0; k < 10; k++) {
                ag = fma2(h2[k], w2[2][k], ag);
                ai = fma2(h2[k], w2[0][k], ai);
                af = fma2(h2[k], w2[1][k], af);
                ao = fma2(h2[k], w2[3][k], ao);
            }

            float agA, agB, aiA, aiB, afA, afB, aoA, aoB;
            unpack2(ag, agA, agB);
            unpack2(ai, aiA, aiB);
            unpack2(af, afA, afB);
            unpack2(ao, aoA, aoB);

            const float tgA = tanh_a(agA), tgB = tanh_a(agB);
            const float tiA = tanh_a(aiA), tiB = tanh_a(aiB);
            const float tfA = tanh_a(afA), tfB = tanh_a(afB);
            const float toA = tanh_a(aoA), toB = tanh_a(aoB);

            // i = 0.5*ti+0.5, f = 0.5*tf+0.5, c = f*c + i*g, h' = to*tc + tc.
            const unsigned long long ti2 = pack2(tiA, tiB);
            const unsigned long long tf2 = pack2(tfA, tfB);
            const unsigned long long tg2 = pack2(tgA, tgB);
            const unsigned long long i2  = fma2(half2, ti2, half2);
            const unsigned long long f2  = fma2(half2, tf2, half2);
            const unsigned long long ig2 = mul2(i2, tg2);
            c2 = fma2(f2, c2, ig2);

            float cA, cB;
            unpack2(c2, cA, cB);
            const float tcA = tanh_a(cA);
            const float tcB = tanh_a(cB);
            hA = fmaf(toA, tcA, tcA);
            hB = fmaf(toB, tcB, tcB);

            // Broadcast h' through shared memory (parity double-buffered).
            const unsigned long long hself = pack2(hA, hB);
            if ((u & 1) == 0) {
                *myst0 = hself;
                __syncwarp();
#pragma unroll
                for (int m = 0; m < 5; m++) {
                    const ulonglong2 v = grp0[m];
                    h2[2 * m] = v.x;
                    h2[2 * m + 1] = v.y;
                }
            } else {
                *myst1 = hself;
                __syncwarp();
#pragma unroll
                for (int m = 0; m < 5; m++) {
                    const ulonglong2 v = grp1[m];
                    h2[2 * m] = v.x;
                    h2[2 * m + 1] = v.y;
                }
            }
        }
    }

    // ---- Epilogue: out[b] = h . W_out + b_out, with h = 0.5*h'.
    const float wo = W_out[j] * 0.5f;
    const float pA = hA * wo;
    const float pB = hB * wo;
    float sA = 0.f, sB = 0.f;
#pragma unroll
    for (int k = 0; k < 10; k++) {
        sA += __shfl_sync(FULL_MASK, pA, base + k);
        sB += __shfl_sync(FULL_MASK, pB, base + k);
    }
    if (active && j == 0) {
        const float bo = b_out[0];
        out[bA] = sA + bo;
        out[bB] = sB + bo;
    }
}

extern "C" void kernel_launch(void* const* d_in, const int* in_sizes, int n_in,
                              void* d_out, int out_size) {
    (void)in_sizes; (void)n_in; (void)out_size;
    const float* x     = (const float*)d_in[0];
    const float* W_ih  = (const float*)d_in[1];
    const float* W_hh  = (const float*)d_in[2];
    const float* b_ih  = (const float*)d_in[3];
    const float* b_hh  = (const float*)d_in[4];
    const float* W_out = (const float*)d_in[5];
    const float* b_out = (const float*)d_in[6];
    float* out = (float*)d_out;

    const int nblocks = (NGROUPS + GROUPS_PER_BLOCK - 1) / GROUPS_PER_BLOCK; // 86
    lstm_kernel<<<nblocks, THREADS>>>(x, W_ih, W_hh, b_ih, b_hh, W_out, b_out, out);
}

// round 5
// speedup vs baseline: 1.6563x; 1.0268x over previous
#include <cuda_runtime.h>
#include <stdint.h>

// LSTM, B=4096, T=2048, I=1, H=10.
// Round 5: identical math to round 4 (smem h-broadcast, tanh-only activations,
// h'=2h folding) + ANTI-PHASE STAGGER: odd warps run a ~150-cycle dependent
// FMA delay chain before the time loop so the two warps sharing each SMSP run
// half-a-step out of phase (FMA burst of one overlaps MUFU burst of the other)
// instead of colliding on the same pipe every step.

#define FULL_MASK 0xFFFFFFFFu

constexpr int Bv = 4096;
constexpr int Tv = 2048;
constexpr int Hv = 10;
constexpr int NGROUPS = Bv / 2;            // 2048 batch-pairs
constexpr int WARPS_PER_BLOCK = 8;
constexpr int GROUPS_PER_BLOCK = WARPS_PER_BLOCK * 3;  // 24
constexpr int THREADS = WARPS_PER_BLOCK * 32;          // 256

__device__ __forceinline__ unsigned long long pack2(float lo, float hi) {
    unsigned long long r;
    asm("mov.b64 %0, {%1, %2};" : "=l"(r) : "f"(lo), "f"(hi));
    return r;
}
__device__ __forceinline__ void unpack2(unsigned long long v, float& lo, float& hi) {
    asm("mov.b64 {%0, %1}, %2;" : "=f"(lo), "=f"(hi) : "l"(v));
}
__device__ __forceinline__ unsigned long long fma2(unsigned long long a,
                                                   unsigned long long b,
                                                   unsigned long long c) {
    unsigned long long d;
    asm("fma.rn.f32x2 %0, %1, %2, %3;" : "=l"(d) : "l"(a), "l"(b), "l"(c));
    return d;
}
__device__ __forceinline__ unsigned long long mul2(unsigned long long a,
                                                   unsigned long long b) {
    unsigned long long d;
    asm("mul.rn.f32x2 %0, %1, %2;" : "=l"(d) : "l"(a), "l"(b));
    return d;
}
__device__ __forceinline__ float tanh_a(float x) {
    float r; asm("tanh.approx.f32 %0, %1;" : "=f"(r) : "f"(x)); return r;
}

__global__ void __launch_bounds__(THREADS, 1)
lstm_kernel(const float* __restrict__ x,
            const float* __restrict__ W_ih,   // [40,1]
            const float* __restrict__ W_hh,   // [40,10]
            const float* __restrict__ b_ih,   // [40]
            const float* __restrict__ b_hh,   // [40]
            const float* __restrict__ W_out,  // [1,10]
            const float* __restrict__ b_out,  // [1]
            float* __restrict__ out)          // [4096]
{
    // Double-buffered h exchange: [parity][warp][group][unit], 12-ull stride
    // (96B) keeps LDS.128 16B-aligned and groups on distinct banks.
    __shared__ __align__(16) unsigned long long hbuf[2][WARPS_PER_BLOCK][4][12];

    const int warp = threadIdx.x >> 5;
    const int lane = threadIdx.x & 31;
    // Whole-warp early exit (no block-wide barriers are used).
    if (blockIdx.x * GROUPS_PER_BLOCK + warp * 3 >= NGROUPS) return;

    const int g    = lane / 10;               // 0..2 real groups, 3 = idle lanes
    const int j    = lane - g * 10;           // hidden unit owned by this lane
    const int base = g * 10;
    const int slot = blockIdx.x * GROUPS_PER_BLOCK + warp * 3 + g;
    const bool active = (g < 3) && (slot < NGROUPS);
    const int s  = active ? slot : 0;
    const int bA = 2 * s;
    const int bB = 2 * s + 1;

    // ---- Per-lane weights (rows q*10+j, gate order i,f,g,o).
    // Sigmoid gates (q=0,1,3): pre-scaled by 0.5. h is h'=2h -> W_hh *0.5 more.
    unsigned long long w2[4][10], bias2[4], wih2[4];
#pragma unroll
    for (int q = 0; q < 4; q++) {
        const float gs = (q == 2) ? 1.0f : 0.5f;
        const int row = q * 10 + j;
        const float bb = (b_ih[row] + b_hh[row]) * gs;
        bias2[q] = pack2(bb, bb);
        const float wi = W_ih[row] * gs;           // I == 1
        wih2[q] = pack2(wi, wi);
        const float hs = gs * 0.5f;
#pragma unroll
        for (int k = 0; k < 10; k++) {
            const float w = W_hh[row * Hv + k] * hs;
            w2[q][k] = pack2(w, w);
        }
    }
    const unsigned long long half2 = pack2(0.5f, 0.5f);

    // ---- State
    unsigned long long h2[10];
#pragma unroll
    for (int k = 0; k < 10; k++) h2[k] = 0ull;
    unsigned long long c2 = 0ull;
    float hA = 0.f, hB = 0.f;                      // own unit h' (for epilogue)

    unsigned long long* myst0 = &hbuf[0][warp][g][j];
    unsigned long long* myst1 = &hbuf[1][warp][g][j];
    const ulonglong2* grp0 = reinterpret_cast<const ulonglong2*>(&hbuf[0][warp][g][0]);
    const ulonglong2* grp1 = reinterpret_cast<const ulonglong2*>(&hbuf[1][warp][g][0]);

    const float4* xA4 = reinterpret_cast<const float4*>(x + (size_t)bA * Tv);
    const float4* xB4 = reinterpret_cast<const float4*>(x + (size_t)bB * Tv);
    float4 nA = xA4[0], nB = xB4[0];               // double-buffered x

    // ---- ANTI-PHASE STAGGER: odd warps burn ~150 cycles on a dependent FMA
    // chain so the two warps on each SMSP run out of phase for the whole loop.
    // The condition below is never true (d stays >= 1), so no store happens,
    // but the compiler must keep the chain.
    if (warp & 1) {
        float d = 1.0f + (float)lane;
#pragma unroll
        for (int it = 0; it < 37; it++) d = fmaf(d, 1.0000001f, 1.0f);
        if (d == -1.0f) out[0] = d;
    }

    for (int t0 = 0; t0 < Tv; t0 += 4) {
        const float4 curA = nA, curB = nB;
        const int nxt = (t0 >> 2) + 1;
        if (nxt < Tv / 4) { nA = xA4[nxt]; nB = xB4[nxt]; }

#pragma unroll
        for (int u = 0; u < 4; u++) {
            const float xa = (u == 0) ? curA.x : (u == 1) ? curA.y : (u == 2) ? curA.z : curA.w;
            const float xb = (u == 0) ? curB.x : (u == 1) ? curB.y : (u == 2) ? curB.z : curB.w;
            const unsigned long long x2 = pack2(xa, xb);

            // 4 independent 11-deep chains; g and i ordered first (they feed
            // the deepest epilogue path).
            unsigned long long ag = fma2(x2, wih2[2], bias2[2]);
            unsigned long long ai = fma2(x2, wih2[0], bias2[0]);
            unsigned long long af = fma2(x2, wih2[1], bias2[1]);
            unsigned long long ao = fma2(x2, wih2[3], bias2[3]);
#pragma unroll
            for (int k = 0; k < 10; k++) {
                ag = fma2(h2[k], w2[2][k], ag);
                ai = fma2(h2[k], w2[0][k], ai);
                af = fma2(h2[k], w2[1][k], af);
                ao = fma2(h2[k], w2[3][k], ao);
            }

            float agA, agB, aiA, aiB, afA, afB, aoA, aoB;
            unpack2(ag, agA, agB);
            unpack2(ai, aiA, aiB);
            unpack2(af, afA, afB);
            unpack2(ao, aoA, aoB);

            const float tgA = tanh_a(agA), tgB = tanh_a(agB);
            const float tiA = tanh_a(aiA), tiB = tanh_a(aiB);
            const float tfA = tanh_a(afA), tfB = tanh_a(afB);
            const float toA = tanh_a(aoA), toB = tanh_a(aoB);

            // i = 0.5*ti+0.5, f = 0.5*tf+0.5, c = f*c + i*g, h' = to*tc + tc.
            const unsigned long long ti2 = pack2(tiA, tiB);
            const unsigned long long tf2 = pack2(tfA, tfB);
            const unsigned long long tg2 = pack2(tgA, tgB);
            const unsigned long long i2  = fma2(half2, ti2, half2);
            const unsigned long long f2  = fma2(half2, tf2, half2);
            const unsigned long long ig2 = mul2(i2, tg2);
            c2 = fma2(f2, c2, ig2);

            float cA, cB;
            unpack2(c2, cA, cB);
            const float tcA = tanh_a(cA);
            const float tcB = tanh_a(cB);
            hA = fmaf(toA, tcA, tcA);
            hB = fmaf(toB, tcB, tcB);

            // Broadcast h' through shared memory (parity double-buffered).
            const unsigned long long hself = pack2(hA, hB);
            if ((u & 1) == 0) {
                *myst0 = hself;
                __syncwarp();
#pragma unroll
                for (int m = 0; m < 5; m++) {
                    const ulonglong2 v = grp0[m];
                    h2[2 * m] = v.x;
                    h2[2 * m + 1] = v.y;
                }
            } else {
                *myst1 = hself;
                __syncwarp();
#pragma unroll
                for (int m = 0; m < 5; m++) {
                    const ulonglong2 v = grp1[m];
                    h2[2 * m] = v.x;
                    h2[2 * m + 1] = v.y;
                }
            }
        }
    }

    // ---- Epilogue: out[b] = h . W_out + b_out, with h = 0.5*h'.
    const float wo = W_out[j] * 0.5f;
    const float pA = hA * wo;
    const float pB = hB * wo;
    float sA = 0.f, sB = 0.f;
#pragma unroll
    for (int k = 0; k < 10; k++) {
        sA += __shfl_sync(FULL_MASK, pA, base + k);
        sB += __shfl_sync(FULL_MASK, pB, base + k);
    }
    if (active && j == 0) {
        const float bo = b_out[0];
        out[bA] = sA + bo;
        out[bB] = sB + bo;
    }
}

extern "C" void kernel_launch(void* const* d_in, const int* in_sizes, int n_in,
                              void* d_out, int out_size) {
    (void)in_sizes; (void)n_in; (void)out_size;
    const float* x     = (const float*)d_in[0];
    const float* W_ih  = (const float*)d_in[1];
    const float* W_hh  = (const float*)d_in[2];
    const float* b_ih  = (const float*)d_in[3];
    const float* b_hh  = (const float*)d_in[4];
    const float* W_out = (const float*)d_in[5];
    const float* b_out = (const float*)d_in[6];
    float* out = (float*)d_out;

    const int nblocks = (NGROUPS + GROUPS_PER_BLOCK - 1) / GROUPS_PER_BLOCK; // 86
    lstm_kernel<<<nblocks, THREADS>>>(x, W_ih, W_hh, b_ih, b_hh, W_out, b_out, out);
}